// round 15
// baseline (speedup 1.0000x reference)
#include <cuda_runtime.h>

// Problem constants
#define B_   32
#define T_   512
#define IN_  512
#define OUT_ 512
#define LH_  512
#define OUT_OFS (B_ * T_ * OUT_)          // start of h_n in d_out
#define HN_ELEMS (4 * B_ * LH_)           // 65536

#define NB   148
#define NTPB 768
#define NT   (NB * NTPB)

// dynamic smem layout (floats)
#define PART_F 12288                      // 12 slices x 32 rows x 32 b
#define WS_F   12288                      // 12 slices x 2 buf x 8 kp x 64
#define AS_F   12288                      // 12 slices x 2 buf x 8 kp x 64
#define SMEM_BYTES ((PART_F + WS_F + AS_F) * 4)   // 147456

// ---------------------------------------------------------------------------
// Persistent device scratch — K-PAIR PACKED layouts (f32x2-native):
// g_wT[l][kp][p][s]: weight for k = 2*kp+s at permuted row p = d*2048+j*4+gate.
//   kp < 512 -> W_ih ; kp >= 512 -> W_hh (k-1024).
// Act buffers [par][d][kp][b][s]: value for k = 2*kp+s, batch b.
// a0: kp<256 x_t | 256..511 prev | 512..767 h_rec
// a1: kp<512 h0 (f|b)            | 512..767 h_rec
// ---------------------------------------------------------------------------
__device__ __align__(16) float g_xT[T_][256][B_][2];       // 32 MB [t][kp][b][s]
__device__ __align__(16) float g_wT[2][768][8192];         // 50 MB [l][kp][p*2+s]
__device__ __align__(16) float g_wfcT[1024][512];          // 2 MB  [k][o]
__device__ __align__(16) float g_bias[2][4096];            // permuted b_ih+b_hh
__device__ __align__(16) float g_a0[2][2][768][B_][2];
__device__ __align__(16) float g_a1[2][2][768][B_][2];
__device__ __align__(16) float g_afc[1024][B_];
__device__ float g_c[2][2][LH_][B_];                       // [l][d][j][b]

__device__ unsigned g_count;
__device__ volatile unsigned g_gen;

__device__ __forceinline__ float sigmoidf_(float x) {
    return 1.0f / (1.0f + __expf(-x));
}

// ---- packed f32x2 helpers (FFMA2 path, sm_103a) ----
__device__ __forceinline__ void ffma2(unsigned long long& d,
                                      unsigned long long a, unsigned long long b) {
    asm("fma.rn.f32x2 %0, %1, %2, %0;" : "+l"(d) : "l"(a), "l"(b));
}
__device__ __forceinline__ float2 upk2(unsigned long long v) {
    float2 f;
    asm("mov.b64 {%0, %1}, %2;" : "=f"(f.x), "=f"(f.y) : "l"(v));
    return f;
}

// ---- cp.async helpers ----
__device__ __forceinline__ void cp16(unsigned s, const float* g) {
    asm volatile("cp.async.cg.shared.global [%0], [%1], 16;"
                 :: "r"(s), "l"(__cvta_generic_to_global(g)) : "memory");
}
__device__ __forceinline__ void cpcommit() {
    asm volatile("cp.async.commit_group;" ::: "memory");
}
__device__ __forceinline__ void cpwait1() {
    asm volatile("cp.async.wait_group 1;" ::: "memory");
}
__device__ __forceinline__ void cpwait0() {
    asm volatile("cp.async.wait_group 0;" ::: "memory");
}
__device__ __forceinline__ void barslice(int sid) {   // 64-thread named barrier
    asm volatile("bar.sync %0, 64;" :: "r"(sid + 1) : "memory");
}
__device__ __forceinline__ unsigned s2u(const void* p) {
    return (unsigned)__cvta_generic_to_shared(p);
}

// Grid-wide sense-reversing barrier (all 148 CTAs co-resident, 1/SM).
__device__ __forceinline__ void gbar() {
    __syncthreads();
    if (threadIdx.x == 0) {
        unsigned gen = g_gen;
        __threadfence();
        if (atomicAdd(&g_count, 1u) == NB - 1) {
            g_count = 0;
            __threadfence();
            g_gen = gen + 1;
        } else {
            while (g_gen == gen) { __nanosleep(32); }
        }
        __threadfence();
    }
    __syncthreads();
}

// ---------------------------------------------------------------------------
// Gate stage for layer L (both dirs): GEMM [4096 rows x K=1536] x [1536 x 32b]
// 128 blocks x 32 rows; 12 k-slices (64 kp each) x 64 threads; micro-tile
// 4 rows x 4 b. cp.async double buffering in chunks of 8 kp (16 k).
// Inner loop: 4 LDS.128 + 16 FFMA2 per kp — ZERO pack MOVs (k-pair layout).
// ---------------------------------------------------------------------------
template <int L>
__device__ __forceinline__ void gate_stage(int par, float* part, float* ws, float* as) {
    const int blk = blockIdx.x;
    if (blk >= 128) return;           // idle blocks fall through to gbar
    const int tid   = threadIdx.x;
    const int slice = tid >> 6;       // 0..11
    const int t64   = tid & 63;
    const int bg    = t64 & 7;
    const int rg    = t64 >> 3;       // 0..7
    const int d     = blk >> 6;
    const int c0    = t64 >> 4;       // copy: kp_local 0..3 (and +4)
    const int f0    = (t64 & 15) * 4; // copy: float offset within 64-float row

    const float* wbase = (const float*)g_wT + (size_t)L * 768 * 8192 + blk * 64;
    const float* abase = (L == 0 ? &g_a0[par][d][0][0][0] : &g_a1[par][d][0][0][0]);

    const float* wsrc0 = wbase + (slice * 64 + c0) * 8192 + f0;
    const float* asrc0 = abase + (slice * 64 + c0) * 64 + f0;

    const unsigned wdst0 = s2u(ws) + (unsigned)((slice * 1024 + c0 * 64 + f0) * 4);
    const unsigned adst0 = s2u(as) + (unsigned)((slice * 1024 + c0 * 64 + f0) * 4);

    // prefetch chunk 0 -> buf 0 (each thread: kp rows c0 and c0+4, 16B col f0)
    cp16(wdst0, wsrc0);         cp16(wdst0 + 1024, wsrc0 + 4 * 8192);
    cp16(adst0, asrc0);         cp16(adst0 + 1024, asrc0 + 256);
    cpcommit();

    unsigned long long A00=0,A01=0,A02=0,A03=0, A10=0,A11=0,A12=0,A13=0,
                       A20=0,A21=0,A22=0,A23=0, A30=0,A31=0,A32=0,A33=0;

    const float* wsb = ws + slice * 1024 + rg * 8;
    const float* asb = as + slice * 1024 + bg * 8;

    #pragma unroll 1
    for (int ch = 0; ch < 8; ch++) {
        const int buf = ch & 1;
        if (ch < 7) {
            const float* w2 = wsrc0 + (ch + 1) * 65536;   // 8 kp * 8192
            const float* a2 = asrc0 + (ch + 1) * 512;     // 8 kp * 64
            const unsigned bo = (unsigned)(((ch + 1) & 1) * 2048);
            cp16(wdst0 + bo, w2);  cp16(wdst0 + bo + 1024, w2 + 4 * 8192);
            cp16(adst0 + bo, a2);  cp16(adst0 + bo + 1024, a2 + 256);
            cpcommit();
            cpwait1();
        } else {
            cpwait0();
        }
        barslice(slice);

        const float* wp = wsb + buf * 512;
        const float* ap = asb + buf * 512;
        #pragma unroll
        for (int kpl = 0; kpl < 8; kpl++) {
            ulonglong2 w0  = *(const ulonglong2*)(wp + kpl * 64);       // rows r0,r1
            ulonglong2 w1  = *(const ulonglong2*)(wp + kpl * 64 + 4);   // rows r2,r3
            ulonglong2 av0 = *(const ulonglong2*)(ap + kpl * 64);       // b0,b1
            ulonglong2 av1 = *(const ulonglong2*)(ap + kpl * 64 + 4);   // b2,b3
            ffma2(A00, w0.x, av0.x); ffma2(A01, w0.x, av0.y);
            ffma2(A02, w0.x, av1.x); ffma2(A03, w0.x, av1.y);
            ffma2(A10, w0.y, av0.x); ffma2(A11, w0.y, av0.y);
            ffma2(A12, w0.y, av1.x); ffma2(A13, w0.y, av1.y);
            ffma2(A20, w1.x, av0.x); ffma2(A21, w1.x, av0.y);
            ffma2(A22, w1.x, av1.x); ffma2(A23, w1.x, av1.y);
            ffma2(A30, w1.y, av0.x); ffma2(A31, w1.y, av0.y);
            ffma2(A32, w1.y, av1.x); ffma2(A33, w1.y, av1.y);
        }
        barslice(slice);
    }

    // horizontal add (even-k lane + odd-k lane) and store partials
    {
        float4* p4 = (float4*)part;
        int base = ((slice * 32 + rg * 4) * 32 + bg * 4) >> 2;
        { float2 u0=upk2(A00),u1=upk2(A01),u2=upk2(A02),u3=upk2(A03);
          p4[base + 0*8] = make_float4(u0.x+u0.y, u1.x+u1.y, u2.x+u2.y, u3.x+u3.y); }
        { float2 u0=upk2(A10),u1=upk2(A11),u2=upk2(A12),u3=upk2(A13);
          p4[base + 1*8] = make_float4(u0.x+u0.y, u1.x+u1.y, u2.x+u2.y, u3.x+u3.y); }
        { float2 u0=upk2(A20),u1=upk2(A21),u2=upk2(A22),u3=upk2(A23);
          p4[base + 2*8] = make_float4(u0.x+u0.y, u1.x+u1.y, u2.x+u2.y, u3.x+u3.y); }
        { float2 u0=upk2(A30),u1=upk2(A31),u2=upk2(A32),u3=upk2(A33);
          p4[base + 3*8] = make_float4(u0.x+u0.y, u1.x+u1.y, u2.x+u2.y, u3.x+u3.y); }
    }
    __syncthreads();

    if (tid < 256) {
        const int j8 = tid >> 5;
        const int b  = tid & 31;
        float g[4];
        #pragma unroll
        for (int gate = 0; gate < 4; gate++) {
            int r = j8 * 4 + gate;
            float v = g_bias[L][blk * 32 + r];
            #pragma unroll
            for (int s = 0; s < 12; s++) v += part[(s * 32 + r) * 32 + b];
            g[gate] = v;
        }
        const int j = (blk & 63) * 8 + j8;
        float co = g_c[L][d][j][b];
        float cn = sigmoidf_(g[1]) * co + sigmoidf_(g[0]) * tanhf(g[2]);
        float hn = sigmoidf_(g[3]) * tanhf(cn);
        g_c[L][d][j][b] = cn;
        if (L == 0) {
            int k = d * 512 + j;                       // h0 position (k-pair layout)
            g_a1[par][0][k >> 1][b][k & 1] = hn;
            g_a1[par][1][k >> 1][b][k & 1] = hn;
            g_a0[par ^ 1][d][512 + (j >> 1)][b][j & 1] = hn;   // h_rec
        } else {
            g_afc[d * 512 + j][b] = hn;                        // FC input
            g_a1[par ^ 1][d][512 + (j >> 1)][b][j & 1] = hn;   // h_rec
        }
    }
}

// ---------------------------------------------------------------------------
// Single persistent kernel.
// ---------------------------------------------------------------------------
__global__ void __launch_bounds__(NTPB, 1) encoder_persistent(
    const float* __restrict__ in_seq,
    const float* __restrict__ W_ih, const float* __restrict__ W_hh,
    const float* __restrict__ b_ih, const float* __restrict__ b_hh,
    const float* __restrict__ W_fc, const float* __restrict__ b_fc,
    float* __restrict__ out)
{
    extern __shared__ float sm[];
    float* part = sm;                 // 48 KB
    float* ws   = sm + PART_F;        // 48 KB
    float* as   = sm + PART_F + WS_F; // 48 KB
    const int gtid = blockIdx.x * NTPB + threadIdx.x;

    // ===== init phase (runs every replay) =====
    // 1) xT[t][kp][b][s] <- in_seq[b][t][2kp+s]
    for (int i = gtid; i < T_ * 16384; i += NT) {
        int s = i & 1, b = (i >> 1) & 31, kp = (i >> 6) & 255, t = i >> 14;
        ((float*)g_xT)[i] = in_seq[((b << 9) | t) * 512 + kp * 2 + s];
    }
    // 2) gate weights W_ih part -> kp 0..511
    for (int i = gtid; i < 2 * 4096 * 256; i += NT) {
        int k4 = i & 255, rr = i >> 8;
        int l = rr >> 12, dgj = rr & 4095;
        int d = dgj >> 11, gate = (dgj >> 9) & 3, j = dgj & 511;
        int wrow = (l * 2 + d) * 2048 + gate * 512 + j;
        float4 w = ((const float4*)W_ih)[wrow * 256 + k4];
        int pp = (d * 2048 + j * 4 + gate) * 2;
        float* wl = (float*)g_wT + (size_t)l * 768 * 8192;
        wl[(2 * k4) * 8192 + pp]         = w.x;
        wl[(2 * k4) * 8192 + pp + 1]     = w.y;
        wl[(2 * k4 + 1) * 8192 + pp]     = w.z;
        wl[(2 * k4 + 1) * 8192 + pp + 1] = w.w;
    }
    // 3) gate weights W_hh part -> kp 512..767
    for (int i = gtid; i < 2 * 4096 * 128; i += NT) {
        int k4 = i & 127, rr = i >> 7;
        int l = rr >> 12, dgj = rr & 4095;
        int d = dgj >> 11, gate = (dgj >> 9) & 3, j = dgj & 511;
        int wrow = (l * 2 + d) * 2048 + gate * 512 + j;
        float4 w = ((const float4*)W_hh)[wrow * 128 + k4];
        int pp = (d * 2048 + j * 4 + gate) * 2;
        float* wl = (float*)g_wT + (size_t)l * 768 * 8192;
        wl[(512 + 2 * k4) * 8192 + pp]         = w.x;
        wl[(512 + 2 * k4) * 8192 + pp + 1]     = w.y;
        wl[(512 + 2 * k4 + 1) * 8192 + pp]     = w.z;
        wl[(512 + 2 * k4 + 1) * 8192 + pp + 1] = w.w;
    }
    // 4) FC weights: wfcT[k][o]
    for (int i = gtid; i < 512 * 256; i += NT) {
        int k4 = i & 255, o = i >> 8;
        float4 w = ((const float4*)W_fc)[o * 256 + k4];
        g_wfcT[k4 * 4 + 0][o] = w.x;
        g_wfcT[k4 * 4 + 1][o] = w.y;
        g_wfcT[k4 * 4 + 2][o] = w.z;
        g_wfcT[k4 * 4 + 3][o] = w.w;
    }
    // 5) biases (permuted)
    for (int i = gtid; i < 2 * 4096; i += NT) {
        int l = i >> 12, p = i & 4095;
        int d = p >> 11, j = (p >> 2) & 511, gate = p & 3;
        int wrow = (l * 2 + d) * 2048 + gate * 512 + j;
        g_bias[l][p] = b_ih[wrow] + b_hh[wrow];
    }
    // 6) zero initial state: a0[0] prev+hrec (kp 256..767), a1[0] hrec (kp 512..767), g_c
    for (int i = gtid; i < 2 * 512 * 64; i += NT) {
        int d = i >> 15;
        (&g_a0[0][d][256][0][0])[i & 0x7FFF] = 0.0f;
    }
    for (int i = gtid; i < 2 * 256 * 64; i += NT) {
        int d = i >> 14;
        (&g_a1[0][d][512][0][0])[i & 0x3FFF] = 0.0f;
    }
    for (int i = gtid; i < 2 * 2 * LH_ * B_; i += NT) ((float*)g_c)[i] = 0.0f;
    // 7) x_0 into a0[0]
    for (int i = gtid; i < 512 * B_; i += NT) {
        int b = i & 31, k = i >> 5;
        float v = in_seq[(b << 18) + k];   // t = 0
        g_a0[0][0][k >> 1][b][k & 1] = v;
        g_a0[0][1][k >> 1][b][k & 1] = v;
    }
    gbar();

    // ===== time loop =====
    for (int t = 0; t < T_; t++) {
        const int par = t & 1;

        gate_stage<0>(par, part, ws, as);
        gbar();
        gate_stage<1>(par, part, ws, as);
        gbar();

        // FC head (blocks 0..63) + x_{t+1} copy (blocks 64..147)
        const int blk = blockIdx.x;
        if (blk < 64) {
            const int tid = threadIdx.x;
            if (tid < 512) {
                const int sub = tid & 15;
                const int slice = tid >> 4;          // 0..31, 32 k each
                const int bgrp = sub & 7;
                const int rowgrp = sub >> 3;         // 0..1
                const float4* __restrict__ w4 = (const float4*)
                    (&g_wfcT[slice * 32][blk * 8 + rowgrp * 4]);
                const float4* __restrict__ a4 = (const float4*)
                    (&g_afc[slice * 32][bgrp * 4]);
                float c00=0,c01=0,c02=0,c03=0, c10=0,c11=0,c12=0,c13=0;
                float c20=0,c21=0,c22=0,c23=0, c30=0,c31=0,c32=0,c33=0;
                #pragma unroll 8
                for (int i = 0; i < 32; i++) {
                    float4 w = w4[i * 128];          // wfcT row stride = 512
                    float4 a = a4[i * 8];
                    c00 += w.x*a.x; c01 += w.x*a.y; c02 += w.x*a.z; c03 += w.x*a.w;
                    c10 += w.y*a.x; c11 += w.y*a.y; c12 += w.y*a.z; c13 += w.y*a.w;
                    c20 += w.z*a.x; c21 += w.z*a.y; c22 += w.z*a.z; c23 += w.z*a.w;
                    c30 += w.w*a.x; c31 += w.w*a.y; c32 += w.w*a.z; c33 += w.w*a.w;
                }
                float4* p4 = (float4*)part;
                int base = (slice * 8 + rowgrp * 4) * 32 + bgrp * 4;
                p4[(base >> 2) + 0*8] = make_float4(c00, c01, c02, c03);
                p4[(base >> 2) + 1*8] = make_float4(c10, c11, c12, c13);
                p4[(base >> 2) + 2*8] = make_float4(c20, c21, c22, c23);
                p4[(base >> 2) + 3*8] = make_float4(c30, c31, c32, c33);
            }
            __syncthreads();
            if (threadIdx.x < 256) {
                const int r = threadIdx.x >> 5;
                const int b = threadIdx.x & 31;
                const int o = blk * 8 + r;
                float v = b_fc[o];
                #pragma unroll
                for (int s = 0; s < 32; s++) v += part[(s * 8 + r) * 32 + b];
                out[((b << 9) | t) * 512 + o] = v;                 // outputs[b][t][o]
                g_a0[par ^ 1][0][256 + (o >> 1)][b][o & 1] = v;    // prev (k=512+o)
                g_a0[par ^ 1][1][256 + (o >> 1)][b][o & 1] = v;
            }
        } else if (t + 1 < T_) {
            // copy x_{t+1} into next-parity act buffers (both dirs), kp 0..255
            int idx = (blk - 64) * NTPB + threadIdx.x;
            if (idx < 4096) {                                      // 16384 floats
                const float4* xs = (const float4*)(&g_xT[t + 1][0][0][0]);
                float4 v = xs[idx];
                ((float4*)(&g_a0[par ^ 1][0][0][0][0]))[idx] = v;
                ((float4*)(&g_a0[par ^ 1][1][0][0][0]))[idx] = v;
            }
        }
        gbar();
    }

    // ===== final h_n / c_n =====
    // last step t=511 (par=1) wrote h_rec into buffers[0]
    for (int i = gtid; i < 65536; i += NT) {
        int b = i & 31, j = (i >> 5) & 511, d = (i >> 14) & 1, l = i >> 15;
        float h = (l == 0 ? g_a0[0][d][512 + (j >> 1)][b][j & 1]
                          : g_a1[0][d][512 + (j >> 1)][b][j & 1]);
        float c = g_c[l][d][j][b];
        int ofs = (((l * 2 + d) * B_) + b) * LH_ + j;
        out[OUT_OFS + ofs] = h;
        out[OUT_OFS + HN_ELEMS + ofs] = c;
    }
}

// ---------------------------------------------------------------------------
// Inputs (metadata order): input_seq, input_lengths, W_ih, W_hh, b_ih, b_hh,
// W_fc, b_fc.
// ---------------------------------------------------------------------------
extern "C" void kernel_launch(void* const* d_in, const int* in_sizes, int n_in,
                              void* d_out, int out_size) {
    (void)in_sizes; (void)n_in; (void)out_size;
    cudaFuncSetAttribute(encoder_persistent,
                         cudaFuncAttributeMaxDynamicSharedMemorySize, SMEM_BYTES);
    encoder_persistent<<<NB, NTPB, SMEM_BYTES>>>(
        (const float*)d_in[0],
        (const float*)d_in[2], (const float*)d_in[3],
        (const float*)d_in[4], (const float*)d_in[5],
        (const float*)d_in[6], (const float*)d_in[7],
        (float*)d_out);
}

// round 16
// speedup vs baseline: 1.3211x; 1.3211x over previous
#include <cuda_runtime.h>

// Problem constants
#define B_   32
#define T_   512
#define IN_  512
#define OUT_ 512
#define LH_  512
#define OUT_OFS (B_ * T_ * OUT_)          // start of h_n in d_out
#define HN_ELEMS (4 * B_ * LH_)           // 65536

#define NB   148
#define NTPB 768
#define NT   (NB * NTPB)

// dynamic smem layout (floats)
#define PART_F 12288                      // 12 slices x 32 rows x 32 b
#define WS_F   12288                      // 12 slices x 2 buf x 8 kp x 64
#define AS_F   12288                      // 12 slices x 2 buf x 8 kp x 64
#define SMEM_BYTES ((PART_F + WS_F + AS_F) * 4)   // 147456

// ---------------------------------------------------------------------------
// Persistent device scratch — K-PAIR PACKED + HALF-SPLIT rows (f32x2-native,
// 128B-warp-footprint LDS):
// Weight row (per kp, per 32-row block): 64 floats =
//   [0..31]  : for rg 0..7 -> rows (4rg+0, 4rg+1) x (s0,s1)   (the w0 load)
//   [32..63] : for rg 0..7 -> rows (4rg+2, 4rg+3) x (s0,s1)   (the w1 load)
// Act row (per kp): 64 floats =
//   [0..31]  : for bg 0..7 -> batches (4bg+0,4bg+1) x (s0,s1) (av0)
//   [32..63] : for bg 0..7 -> batches (4bg+2,4bg+3) x (s0,s1) (av1)
// k-pair: kp<512 -> W_ih k=2kp+s ; kp>=512 -> W_hh. Acts: kp rows as before:
// a0: kp<256 x_t | 256..511 prev | 512..767 h_rec ; a1: h0 | h_rec.
// ---------------------------------------------------------------------------
__device__ __align__(16) float g_xT[T_][256][64];          // 32 MB
__device__ __align__(16) float g_wT[2][768][8192];         // 50 MB
__device__ __align__(16) float g_wfcT[1024][512];          // 2 MB  [k][o]
__device__ __align__(16) float g_bias[2][4096];            // permuted b_ih+b_hh
__device__ __align__(16) float g_a0[2][2][768][64];
__device__ __align__(16) float g_a1[2][2][768][64];
__device__ __align__(16) float g_afc[1024][B_];
__device__ float g_c[2][2][LH_][B_];                       // [l][d][j][b]

__device__ unsigned g_count;
__device__ volatile unsigned g_gen;

__device__ __forceinline__ float sigmoidf_(float x) {
    return 1.0f / (1.0f + __expf(-x));
}

// position of (batch b, k-parity s) within a 64-float act row (half-split)
__device__ __forceinline__ int actpos(int b, int s) {
    return ((b & 2) ? 32 : 0) + (b >> 2) * 4 + (b & 1) * 2 + s;
}

// ---- packed f32x2 helpers (FFMA2 path, sm_103a) ----
__device__ __forceinline__ void ffma2(unsigned long long& d,
                                      unsigned long long a, unsigned long long b) {
    asm("fma.rn.f32x2 %0, %1, %2, %0;" : "+l"(d) : "l"(a), "l"(b));
}
__device__ __forceinline__ float2 upk2(unsigned long long v) {
    float2 f;
    asm("mov.b64 {%0, %1}, %2;" : "=f"(f.x), "=f"(f.y) : "l"(v));
    return f;
}

// ---- cp.async helpers ----
__device__ __forceinline__ void cp16(unsigned s, const float* g) {
    asm volatile("cp.async.cg.shared.global [%0], [%1], 16;"
                 :: "r"(s), "l"(__cvta_generic_to_global(g)) : "memory");
}
__device__ __forceinline__ void cpcommit() {
    asm volatile("cp.async.commit_group;" ::: "memory");
}
__device__ __forceinline__ void cpwait1() {
    asm volatile("cp.async.wait_group 1;" ::: "memory");
}
__device__ __forceinline__ void cpwait0() {
    asm volatile("cp.async.wait_group 0;" ::: "memory");
}
__device__ __forceinline__ void barslice(int sid) {   // 64-thread named barrier
    asm volatile("bar.sync %0, 64;" :: "r"(sid + 1) : "memory");
}
__device__ __forceinline__ unsigned s2u(const void* p) {
    return (unsigned)__cvta_generic_to_shared(p);
}

// Grid-wide sense-reversing barrier (all 148 CTAs co-resident, 1/SM).
__device__ __forceinline__ void gbar() {
    __syncthreads();
    if (threadIdx.x == 0) {
        unsigned gen = g_gen;
        __threadfence();
        if (atomicAdd(&g_count, 1u) == NB - 1) {
            g_count = 0;
            __threadfence();
            g_gen = gen + 1;
        } else {
            while (g_gen == gen) { __nanosleep(32); }
        }
        __threadfence();
    }
    __syncthreads();
}

// ---------------------------------------------------------------------------
// Gate stage for layer L (both dirs): GEMM [4096 rows x K=1536] x [1536 x 32b]
// 128 blocks x 32 rows; 12 k-slices (64 kp each) x 64 threads; micro-tile
// 4 rows x 4 b. cp.async double buffering in chunks of 8 kp (16 k).
// Inner loop: 4 LDS.128 (each warp footprint <= 128B) + 16 FFMA2 per kp,
// zero pack MOVs.
// ---------------------------------------------------------------------------
template <int L>
__device__ __forceinline__ void gate_stage(int par, float* part, float* ws, float* as) {
    const int blk = blockIdx.x;
    if (blk >= 128) return;           // idle blocks fall through to gbar
    const int tid   = threadIdx.x;
    const int slice = tid >> 6;       // 0..11
    const int t64   = tid & 63;
    const int bg    = t64 & 7;
    const int rg    = t64 >> 3;       // 0..7
    const int d     = blk >> 6;
    const int c0    = t64 >> 4;       // copy: kp_local 0..3 (and +4)
    const int f0    = (t64 & 15) * 4; // copy: float offset within 64-float row

    const float* wbase = (const float*)g_wT + (size_t)L * 768 * 8192 + blk * 64;
    const float* abase = (L == 0 ? &g_a0[par][d][0][0] : &g_a1[par][d][0][0]);

    const float* wsrc0 = wbase + (slice * 64 + c0) * 8192 + f0;
    const float* asrc0 = abase + (slice * 64 + c0) * 64 + f0;

    const unsigned wdst0 = s2u(ws) + (unsigned)((slice * 1024 + c0 * 64 + f0) * 4);
    const unsigned adst0 = s2u(as) + (unsigned)((slice * 1024 + c0 * 64 + f0) * 4);

    // prefetch chunk 0 -> buf 0 (each thread: kp rows c0 and c0+4, 16B col f0)
    cp16(wdst0, wsrc0);         cp16(wdst0 + 1024, wsrc0 + 4 * 8192);
    cp16(adst0, asrc0);         cp16(adst0 + 1024, asrc0 + 256);
    cpcommit();

    unsigned long long A00=0,A01=0,A02=0,A03=0, A10=0,A11=0,A12=0,A13=0,
                       A20=0,A21=0,A22=0,A23=0, A30=0,A31=0,A32=0,A33=0;

    const float* wsb = ws + slice * 1024 + rg * 4;
    const float* asb = as + slice * 1024 + bg * 4;

    #pragma unroll 1
    for (int ch = 0; ch < 8; ch++) {
        const int buf = ch & 1;
        if (ch < 7) {
            const float* w2 = wsrc0 + (ch + 1) * 65536;   // 8 kp * 8192
            const float* a2 = asrc0 + (ch + 1) * 512;     // 8 kp * 64
            const unsigned bo = (unsigned)(((ch + 1) & 1) * 2048);
            cp16(wdst0 + bo, w2);  cp16(wdst0 + bo + 1024, w2 + 4 * 8192);
            cp16(adst0 + bo, a2);  cp16(adst0 + bo + 1024, a2 + 256);
            cpcommit();
            cpwait1();
        } else {
            cpwait0();
        }
        barslice(slice);

        const float* wp = wsb + buf * 512;
        const float* ap = asb + buf * 512;
        #pragma unroll
        for (int kpl = 0; kpl < 8; kpl++) {
            ulonglong2 w0  = *(const ulonglong2*)(wp + kpl * 64);        // rows 4rg+0,+1
            ulonglong2 w1  = *(const ulonglong2*)(wp + kpl * 64 + 32);   // rows 4rg+2,+3
            ulonglong2 av0 = *(const ulonglong2*)(ap + kpl * 64);        // b 4bg+0,+1
            ulonglong2 av1 = *(const ulonglong2*)(ap + kpl * 64 + 32);   // b 4bg+2,+3
            ffma2(A00, w0.x, av0.x); ffma2(A01, w0.x, av0.y);
            ffma2(A02, w0.x, av1.x); ffma2(A03, w0.x, av1.y);
            ffma2(A10, w0.y, av0.x); ffma2(A11, w0.y, av0.y);
            ffma2(A12, w0.y, av1.x); ffma2(A13, w0.y, av1.y);
            ffma2(A20, w1.x, av0.x); ffma2(A21, w1.x, av0.y);
            ffma2(A22, w1.x, av1.x); ffma2(A23, w1.x, av1.y);
            ffma2(A30, w1.y, av0.x); ffma2(A31, w1.y, av0.y);
            ffma2(A32, w1.y, av1.x); ffma2(A33, w1.y, av1.y);
        }
        barslice(slice);
    }

    // horizontal add (even-k lane + odd-k lane) and store partials
    // Arc = rows 4rg+r (r=row index within quad), batches 4bg+c.
    {
        float4* p4 = (float4*)part;
        int base = ((slice * 32 + rg * 4) * 32 + bg * 4) >> 2;
        { float2 u0=upk2(A00),u1=upk2(A01),u2=upk2(A02),u3=upk2(A03);
          p4[base + 0*8] = make_float4(u0.x+u0.y, u1.x+u1.y, u2.x+u2.y, u3.x+u3.y); }
        { float2 u0=upk2(A10),u1=upk2(A11),u2=upk2(A12),u3=upk2(A13);
          p4[base + 1*8] = make_float4(u0.x+u0.y, u1.x+u1.y, u2.x+u2.y, u3.x+u3.y); }
        { float2 u0=upk2(A20),u1=upk2(A21),u2=upk2(A22),u3=upk2(A23);
          p4[base + 2*8] = make_float4(u0.x+u0.y, u1.x+u1.y, u2.x+u2.y, u3.x+u3.y); }
        { float2 u0=upk2(A30),u1=upk2(A31),u2=upk2(A32),u3=upk2(A33);
          p4[base + 3*8] = make_float4(u0.x+u0.y, u1.x+u1.y, u2.x+u2.y, u3.x+u3.y); }
    }
    __syncthreads();

    if (tid < 256) {
        const int j8 = tid >> 5;
        const int b  = tid & 31;
        float g[4];
        #pragma unroll
        for (int gate = 0; gate < 4; gate++) {
            int r = j8 * 4 + gate;
            float v = g_bias[L][blk * 32 + r];
            #pragma unroll
            for (int s = 0; s < 12; s++) v += part[(s * 32 + r) * 32 + b];
            g[gate] = v;
        }
        const int j = (blk & 63) * 8 + j8;
        float co = g_c[L][d][j][b];
        float cn = sigmoidf_(g[1]) * co + sigmoidf_(g[0]) * tanhf(g[2]);
        float hn = sigmoidf_(g[3]) * tanhf(cn);
        g_c[L][d][j][b] = cn;
        if (L == 0) {
            int k = d * 512 + j;                      // h0 position
            int c = actpos(b, k & 1);
            g_a1[par][0][k >> 1][c] = hn;
            g_a1[par][1][k >> 1][c] = hn;
            g_a0[par ^ 1][d][512 + (j >> 1)][actpos(b, j & 1)] = hn;  // h_rec
        } else {
            g_afc[d * 512 + j][b] = hn;                               // FC input
            g_a1[par ^ 1][d][512 + (j >> 1)][actpos(b, j & 1)] = hn;  // h_rec
        }
    }
}

// ---------------------------------------------------------------------------
// Single persistent kernel.
// ---------------------------------------------------------------------------
__global__ void __launch_bounds__(NTPB, 1) encoder_persistent(
    const float* __restrict__ in_seq,
    const float* __restrict__ W_ih, const float* __restrict__ W_hh,
    const float* __restrict__ b_ih, const float* __restrict__ b_hh,
    const float* __restrict__ W_fc, const float* __restrict__ b_fc,
    float* __restrict__ out)
{
    extern __shared__ float sm[];
    float* part = sm;                 // 48 KB
    float* ws   = sm + PART_F;        // 48 KB
    float* as   = sm + PART_F + WS_F; // 48 KB
    const int gtid = blockIdx.x * NTPB + threadIdx.x;

    // ===== init phase (runs every replay) =====
    // 1) xT[t][kp][c] with c = actpos(b, s); invert c -> (b, s)
    for (int i = gtid; i < T_ * 16384; i += NT) {
        int c = i & 63, kp = (i >> 6) & 255, t = i >> 14;
        int s = c & 1, qlow = (c >> 1) & 1, bgv = (c >> 2) & 7, hi = (c >> 5) & 1;
        int b = bgv * 4 + hi * 2 + qlow;
        ((float*)g_xT)[i] = in_seq[((b << 9) | t) * 512 + kp * 2 + s];
    }
    // 2) gate weights W_ih part -> kp 0..511 (half-split row permutation)
    for (int i = gtid; i < 2 * 4096 * 256; i += NT) {
        int k4 = i & 255, rr = i >> 8;
        int l = rr >> 12, dgj = rr & 4095;
        int d = dgj >> 11, gate = (dgj >> 9) & 3, j = dgj & 511;
        int wrow = (l * 2 + d) * 2048 + gate * 512 + j;
        float4 w = ((const float4*)W_ih)[wrow * 256 + k4];
        int p = d * 2048 + j * 4 + gate;
        int r = p & 31, rgv = r >> 2, q = r & 3;
        int cb = ((q & 2) ? 32 : 0) + rgv * 4 + (q & 1) * 2;
        float* wl = (float*)g_wT + (size_t)l * 768 * 8192 + (p >> 5) * 64;
        wl[(2 * k4) * 8192 + cb]         = w.x;
        wl[(2 * k4) * 8192 + cb + 1]     = w.y;
        wl[(2 * k4 + 1) * 8192 + cb]     = w.z;
        wl[(2 * k4 + 1) * 8192 + cb + 1] = w.w;
    }
    // 3) gate weights W_hh part -> kp 512..767
    for (int i = gtid; i < 2 * 4096 * 128; i += NT) {
        int k4 = i & 127, rr = i >> 7;
        int l = rr >> 12, dgj = rr & 4095;
        int d = dgj >> 11, gate = (dgj >> 9) & 3, j = dgj & 511;
        int wrow = (l * 2 + d) * 2048 + gate * 512 + j;
        float4 w = ((const float4*)W_hh)[wrow * 128 + k4];
        int p = d * 2048 + j * 4 + gate;
        int r = p & 31, rgv = r >> 2, q = r & 3;
        int cb = ((q & 2) ? 32 : 0) + rgv * 4 + (q & 1) * 2;
        float* wl = (float*)g_wT + (size_t)l * 768 * 8192 + (p >> 5) * 64;
        wl[(512 + 2 * k4) * 8192 + cb]         = w.x;
        wl[(512 + 2 * k4) * 8192 + cb + 1]     = w.y;
        wl[(512 + 2 * k4 + 1) * 8192 + cb]     = w.z;
        wl[(512 + 2 * k4 + 1) * 8192 + cb + 1] = w.w;
    }
    // 4) FC weights: wfcT[k][o]
    for (int i = gtid; i < 512 * 256; i += NT) {
        int k4 = i & 255, o = i >> 8;
        float4 w = ((const float4*)W_fc)[o * 256 + k4];
        g_wfcT[k4 * 4 + 0][o] = w.x;
        g_wfcT[k4 * 4 + 1][o] = w.y;
        g_wfcT[k4 * 4 + 2][o] = w.z;
        g_wfcT[k4 * 4 + 3][o] = w.w;
    }
    // 5) biases (permuted)
    for (int i = gtid; i < 2 * 4096; i += NT) {
        int l = i >> 12, p = i & 4095;
        int d = p >> 11, j = (p >> 2) & 511, gate = p & 3;
        int wrow = (l * 2 + d) * 2048 + gate * 512 + j;
        g_bias[l][p] = b_ih[wrow] + b_hh[wrow];
    }
    // 6) zero initial state: a0[0] prev+hrec (kp 256..767), a1[0] hrec (kp 512..767), g_c
    for (int i = gtid; i < 2 * 512 * 64; i += NT) {
        int d = i >> 15;
        (&g_a0[0][d][256][0])[i & 0x7FFF] = 0.0f;
    }
    for (int i = gtid; i < 2 * 256 * 64; i += NT) {
        int d = i >> 14;
        (&g_a1[0][d][512][0])[i & 0x3FFF] = 0.0f;
    }
    for (int i = gtid; i < 2 * 2 * LH_ * B_; i += NT) ((float*)g_c)[i] = 0.0f;
    // 7) x_0 into a0[0]
    for (int i = gtid; i < 512 * B_; i += NT) {
        int b = i & 31, k = i >> 5;
        float v = in_seq[(b << 18) + k];   // t = 0
        int c = actpos(b, k & 1);
        g_a0[0][0][k >> 1][c] = v;
        g_a0[0][1][k >> 1][c] = v;
    }
    gbar();

    // ===== time loop =====
    for (int t = 0; t < T_; t++) {
        const int par = t & 1;

        gate_stage<0>(par, part, ws, as);
        gbar();
        gate_stage<1>(par, part, ws, as);
        gbar();

        // FC head (blocks 0..63) + x_{t+1} copy (blocks 64..147)
        const int blk = blockIdx.x;
        if (blk < 64) {
            const int tid = threadIdx.x;
            if (tid < 512) {
                const int sub = tid & 15;
                const int slice = tid >> 4;          // 0..31, 32 k each
                const int bgrp = sub & 7;
                const int rowgrp = sub >> 3;         // 0..1
                const float4* __restrict__ w4 = (const float4*)
                    (&g_wfcT[slice * 32][blk * 8 + rowgrp * 4]);
                const float4* __restrict__ a4 = (const float4*)
                    (&g_afc[slice * 32][bgrp * 4]);
                float c00=0,c01=0,c02=0,c03=0, c10=0,c11=0,c12=0,c13=0;
                float c20=0,c21=0,c22=0,c23=0, c30=0,c31=0,c32=0,c33=0;
                #pragma unroll 8
                for (int i = 0; i < 32; i++) {
                    float4 w = w4[i * 128];          // wfcT row stride = 512
                    float4 a = a4[i * 8];
                    c00 += w.x*a.x; c01 += w.x*a.y; c02 += w.x*a.z; c03 += w.x*a.w;
                    c10 += w.y*a.x; c11 += w.y*a.y; c12 += w.y*a.z; c13 += w.y*a.w;
                    c20 += w.z*a.x; c21 += w.z*a.y; c22 += w.z*a.z; c23 += w.z*a.w;
                    c30 += w.w*a.x; c31 += w.w*a.y; c32 += w.w*a.z; c33 += w.w*a.w;
                }
                float4* p4 = (float4*)part;
                int base = (slice * 8 + rowgrp * 4) * 32 + bgrp * 4;
                p4[(base >> 2) + 0*8] = make_float4(c00, c01, c02, c03);
                p4[(base >> 2) + 1*8] = make_float4(c10, c11, c12, c13);
                p4[(base >> 2) + 2*8] = make_float4(c20, c21, c22, c23);
                p4[(base >> 2) + 3*8] = make_float4(c30, c31, c32, c33);
            }
            __syncthreads();
            if (threadIdx.x < 256) {
                const int r = threadIdx.x >> 5;
                const int b = threadIdx.x & 31;
                const int o = blk * 8 + r;
                float v = b_fc[o];
                #pragma unroll
                for (int s = 0; s < 32; s++) v += part[(s * 8 + r) * 32 + b];
                out[((b << 9) | t) * 512 + o] = v;                  // outputs[b][t][o]
                int c = actpos(b, o & 1);                           // prev (k=512+o)
                g_a0[par ^ 1][0][256 + (o >> 1)][c] = v;
                g_a0[par ^ 1][1][256 + (o >> 1)][c] = v;
            }
        } else if (t + 1 < T_) {
            // copy x_{t+1} into next-parity act buffers (both dirs), kp 0..255
            int idx = (blk - 64) * NTPB + threadIdx.x;
            if (idx < 4096) {                                       // 16384 floats
                const float4* xs = (const float4*)(&g_xT[t + 1][0][0]);
                float4 v = xs[idx];
                ((float4*)(&g_a0[par ^ 1][0][0][0]))[idx] = v;
                ((float4*)(&g_a0[par ^ 1][1][0][0]))[idx] = v;
            }
        }
        gbar();
    }

    // ===== final h_n / c_n =====
    // last step t=511 (par=1) wrote h_rec into buffers[0]
    for (int i = gtid; i < 65536; i += NT) {
        int b = i & 31, j = (i >> 5) & 511, d = (i >> 14) & 1, l = i >> 15;
        int c = actpos(b, j & 1);
        float h = (l == 0 ? g_a0[0][d][512 + (j >> 1)][c]
                          : g_a1[0][d][512 + (j >> 1)][c]);
        float cc = g_c[l][d][j][b];
        int ofs = (((l * 2 + d) * B_) + b) * LH_ + j;
        out[OUT_OFS + ofs] = h;
        out[OUT_OFS + HN_ELEMS + ofs] = cc;
    }
}

// ---------------------------------------------------------------------------
// Inputs (metadata order): input_seq, input_lengths, W_ih, W_hh, b_ih, b_hh,
// W_fc, b_fc.
// ---------------------------------------------------------------------------
extern "C" void kernel_launch(void* const* d_in, const int* in_sizes, int n_in,
                              void* d_out, int out_size) {
    (void)in_sizes; (void)n_in; (void)out_size;
    cudaFuncSetAttribute(encoder_persistent,
                         cudaFuncAttributeMaxDynamicSharedMemorySize, SMEM_BYTES);
    encoder_persistent<<<NB, NTPB, SMEM_BYTES>>>(
        (const float*)d_in[0],
        (const float*)d_in[2], (const float*)d_in[3],
        (const float*)d_in[4], (const float*)d_in[5],
        (const float*)d_in[6], (const float*)d_in[7],
        (float*)d_out);
}